// round 1
// baseline (speedup 1.0000x reference)
#include <cuda_runtime.h>

#define NUSR 100000
#define NITM 50000
#define NV   150000
#define NE   1000000
#define DIM  64

// ---------------- scratch (static device globals; no allocation) -------------
__device__ float g_all[(size_t)NV * DIM];   // current embeddings (users, then items)
__device__ float g_ef [(size_t)NV * DIM];   // stage-A result  (F for users, E for items)
__device__ float g_y  [(size_t)NV * DIM];   // stage-B result
__device__ int   g_deg[NV];
__device__ float g_isq[NV];                 // deg^-1/2 (0 if deg==0)
__device__ float g_inv[NV];                 // deg^-1   (0 if deg==0)
__device__ int   g_rs [NV + 1];             // CSR row starts (users' lists, then items')
__device__ int   g_cur[NV];                 // scatter cursors
__device__ int   g_col[2 * NE];             // CSR columns (global vertex ids)

// ---------------- CSR build ---------------------------------------------------
__global__ void zero_deg_kernel() {
    int v = blockIdx.x * blockDim.x + threadIdx.x;
    if (v < NV) g_deg[v] = 0;
}

__global__ void deg_kernel(const int* __restrict__ eu, const int* __restrict__ ei) {
    int e = blockIdx.x * blockDim.x + threadIdx.x;
    if (e < NE) {
        atomicAdd(&g_deg[eu[e]], 1);
        atomicAdd(&g_deg[NUSR + ei[e]], 1);
    }
}

__global__ void scales_kernel() {
    int v = blockIdx.x * blockDim.x + threadIdx.x;
    if (v < NV) {
        int d = g_deg[v];
        if (d > 0) {
            float fd = (float)d;
            g_isq[v] = 1.0f / sqrtf(fd);
            g_inv[v] = 1.0f / fd;
        } else {
            g_isq[v] = 0.0f;
            g_inv[v] = 0.0f;
        }
    }
}

// single-block exclusive prefix sum of degrees -> row starts + cursors
__global__ void scan_kernel() {
    __shared__ int sh[1024];
    const int C = 147;  // 1024*147 >= 150000
    int t = threadIdx.x;
    int beg = t * C;
    int end = beg + C; if (end > NV) end = NV; if (beg > NV) beg = NV;
    int s = 0;
    for (int i = beg; i < end; ++i) s += g_deg[i];
    sh[t] = s;
    __syncthreads();
    for (int off = 1; off < 1024; off <<= 1) {
        int v = sh[t];
        int add = (t >= off) ? sh[t - off] : 0;
        __syncthreads();
        sh[t] = v + add;
        __syncthreads();
    }
    int run = sh[t] - s;  // exclusive prefix
    for (int i = beg; i < end; ++i) {
        g_rs[i]  = run;
        g_cur[i] = run;
        run += g_deg[i];
    }
    if (t == 1023) g_rs[NV] = sh[1023];
}

__global__ void scatter_kernel(const int* __restrict__ eu, const int* __restrict__ ei) {
    int e = blockIdx.x * blockDim.x + threadIdx.x;
    if (e < NE) {
        int u = eu[e];
        int i = NUSR + ei[e];
        int p = atomicAdd(&g_cur[u], 1);
        g_col[p] = i;
        int q = atomicAdd(&g_cur[i], 1);
        g_col[q] = u;
    }
}

// ---------------- init: all_embs = concat(u,i); out (mean-accumulator) = same -
__global__ void init_kernel(const float4* __restrict__ ue,
                            const float4* __restrict__ ie,
                            float4* __restrict__ out) {
    int n = blockIdx.x * blockDim.x + threadIdx.x;  // < NV*16
    float4 v = (n < NUSR * 16) ? ue[n] : ie[n - NUSR * 16];
    ((float4*)g_all)[n] = v;
    out[n] = v;
}

// ---------------- gather stages ----------------------------------------------
// STAGE 0 (scaled):   g_ef[v] = inv[v] * sum_{w in N(v)} g_all[w]*isq[w]
// STAGE 1 (unscaled): g_y[v]  =          sum_{w in N(v)} g_ef[w]
template <int STAGE>
__global__ void gather_kernel() {
    int gid = blockIdx.x * blockDim.x + threadIdx.x;  // NV*16 threads
    int v = gid >> 4;
    int c = gid & 15;
    const float4* __restrict__ src =
        (STAGE == 0) ? (const float4*)g_all : (const float4*)g_ef;
    int beg = g_rs[v];
    int end = g_rs[v + 1];
    float4 acc = make_float4(0.f, 0.f, 0.f, 0.f);
    int n = beg;
    for (; n + 4 <= end; n += 4) {
        int w0 = g_col[n + 0], w1 = g_col[n + 1], w2 = g_col[n + 2], w3 = g_col[n + 3];
        float4 a = src[w0 * 16 + c];
        float4 b = src[w1 * 16 + c];
        float4 d2 = src[w2 * 16 + c];
        float4 d3 = src[w3 * 16 + c];
        if (STAGE == 0) {
            float s0 = g_isq[w0], s1 = g_isq[w1], s2 = g_isq[w2], s3 = g_isq[w3];
            acc.x = fmaf(a.x, s0, acc.x); acc.y = fmaf(a.y, s0, acc.y);
            acc.z = fmaf(a.z, s0, acc.z); acc.w = fmaf(a.w, s0, acc.w);
            acc.x = fmaf(b.x, s1, acc.x); acc.y = fmaf(b.y, s1, acc.y);
            acc.z = fmaf(b.z, s1, acc.z); acc.w = fmaf(b.w, s1, acc.w);
            acc.x = fmaf(d2.x, s2, acc.x); acc.y = fmaf(d2.y, s2, acc.y);
            acc.z = fmaf(d2.z, s2, acc.z); acc.w = fmaf(d2.w, s2, acc.w);
            acc.x = fmaf(d3.x, s3, acc.x); acc.y = fmaf(d3.y, s3, acc.y);
            acc.z = fmaf(d3.z, s3, acc.z); acc.w = fmaf(d3.w, s3, acc.w);
        } else {
            acc.x += a.x + b.x + d2.x + d3.x;
            acc.y += a.y + b.y + d2.y + d3.y;
            acc.z += a.z + b.z + d2.z + d3.z;
            acc.w += a.w + b.w + d2.w + d3.w;
        }
    }
    for (; n < end; ++n) {
        int w = g_col[n];
        float4 a = src[w * 16 + c];
        float s = (STAGE == 0) ? g_isq[w] : 1.0f;
        acc.x = fmaf(a.x, s, acc.x);
        acc.y = fmaf(a.y, s, acc.y);
        acc.z = fmaf(a.z, s, acc.z);
        acc.w = fmaf(a.w, s, acc.w);
    }
    if (STAGE == 0) {
        float iv = g_inv[v];
        acc.x *= iv; acc.y *= iv; acc.z *= iv; acc.w *= iv;
        ((float4*)g_ef)[v * 16 + c] = acc;
    } else {
        ((float4*)g_y)[v * 16 + c] = acc;
    }
}

// ---------------- fused dense transform --------------------------------------
// g = Y[v]*isq[v]; x = all[v]
// o1 = leaky( Wgc g + bgc + x ), o2 = leaky( Wbi (x*g) + bbi )
// nv = (o1+o2) / max(||o1+o2||, 1e-12);  all[v]=nv;  out[v]+=nv (finalize: *0.25)
__global__ __launch_bounds__(256) void transform_kernel(
    const float* __restrict__ Wgc, const float* __restrict__ bgc,
    const float* __restrict__ Wbi, const float* __restrict__ bbi,
    float* __restrict__ out, int l, int finalize) {
    __shared__ float sWg[64 * 64];   // transposed: sWg[k*64+j] = Wgc[l][j][k]
    __shared__ float sWb[64 * 64];
    __shared__ float sG[16 * 64];
    __shared__ float sH[16 * 64];
    __shared__ float sbg[64], sbb[64];

    const float* Wg = Wgc + l * 4096;
    const float* Wb = Wbi + l * 4096;
    for (int idx = threadIdx.x; idx < 4096; idx += 256) {
        int j = idx >> 6, k = idx & 63;
        sWg[k * 64 + j] = Wg[idx];
        sWb[k * 64 + j] = Wb[idx];
    }
    if (threadIdx.x < 64) {
        sbg[threadIdx.x] = bgc[l * 64 + threadIdx.x];
        sbb[threadIdx.x] = bbi[l * 64 + threadIdx.x];
    }
    __syncthreads();

    int grp = threadIdx.x >> 4;   // vertex slot 0..15 (2 per warp)
    int c   = threadIdx.x & 15;   // float4 chunk -> outputs j = 4c..4c+3
    float* gb = sG + grp * 64;
    float* hb = sH + grp * 64;

    // NV % 16 == 0 and v0 is a multiple of 16, so every lane's v is valid
    for (int v0 = blockIdx.x * 16; v0 < NV; v0 += gridDim.x * 16) {
        int v = v0 + grp;
        float s = g_isq[v];
        float4 y4 = ((const float4*)g_y)[v * 16 + c];
        float4 x4 = ((const float4*)g_all)[v * 16 + c];
        float4 g4 = make_float4(y4.x * s, y4.y * s, y4.z * s, y4.w * s);
        float4 h4 = make_float4(g4.x * x4.x, g4.y * x4.y, g4.z * x4.z, g4.w * x4.w);
        ((float4*)gb)[c] = g4;
        ((float4*)hb)[c] = h4;
        __syncwarp();

        float4 o1 = *(const float4*)(sbg + 4 * c);
        float4 o2 = *(const float4*)(sbb + 4 * c);
#pragma unroll
        for (int k = 0; k < 64; k += 4) {
            float4 gk = *(const float4*)(gb + k);
            float4 hk = *(const float4*)(hb + k);
            {
                float4 wa = *(const float4*)(sWg + (k + 0) * 64 + 4 * c);
                float4 wbv = *(const float4*)(sWb + (k + 0) * 64 + 4 * c);
                o1.x = fmaf(gk.x, wa.x, o1.x); o1.y = fmaf(gk.x, wa.y, o1.y);
                o1.z = fmaf(gk.x, wa.z, o1.z); o1.w = fmaf(gk.x, wa.w, o1.w);
                o2.x = fmaf(hk.x, wbv.x, o2.x); o2.y = fmaf(hk.x, wbv.y, o2.y);
                o2.z = fmaf(hk.x, wbv.z, o2.z); o2.w = fmaf(hk.x, wbv.w, o2.w);
            }
            {
                float4 wa = *(const float4*)(sWg + (k + 1) * 64 + 4 * c);
                float4 wbv = *(const float4*)(sWb + (k + 1) * 64 + 4 * c);
                o1.x = fmaf(gk.y, wa.x, o1.x); o1.y = fmaf(gk.y, wa.y, o1.y);
                o1.z = fmaf(gk.y, wa.z, o1.z); o1.w = fmaf(gk.y, wa.w, o1.w);
                o2.x = fmaf(hk.y, wbv.x, o2.x); o2.y = fmaf(hk.y, wbv.y, o2.y);
                o2.z = fmaf(hk.y, wbv.z, o2.z); o2.w = fmaf(hk.y, wbv.w, o2.w);
            }
            {
                float4 wa = *(const float4*)(sWg + (k + 2) * 64 + 4 * c);
                float4 wbv = *(const float4*)(sWb + (k + 2) * 64 + 4 * c);
                o1.x = fmaf(gk.z, wa.x, o1.x); o1.y = fmaf(gk.z, wa.y, o1.y);
                o1.z = fmaf(gk.z, wa.z, o1.z); o1.w = fmaf(gk.z, wa.w, o1.w);
                o2.x = fmaf(hk.z, wbv.x, o2.x); o2.y = fmaf(hk.z, wbv.y, o2.y);
                o2.z = fmaf(hk.z, wbv.z, o2.z); o2.w = fmaf(hk.z, wbv.w, o2.w);
            }
            {
                float4 wa = *(const float4*)(sWg + (k + 3) * 64 + 4 * c);
                float4 wbv = *(const float4*)(sWb + (k + 3) * 64 + 4 * c);
                o1.x = fmaf(gk.w, wa.x, o1.x); o1.y = fmaf(gk.w, wa.y, o1.y);
                o1.z = fmaf(gk.w, wa.z, o1.z); o1.w = fmaf(gk.w, wa.w, o1.w);
                o2.x = fmaf(hk.w, wbv.x, o2.x); o2.y = fmaf(hk.w, wbv.y, o2.y);
                o2.z = fmaf(hk.w, wbv.z, o2.z); o2.w = fmaf(hk.w, wbv.w, o2.w);
            }
        }
        __syncwarp();  // matvec reads of sG/sH complete before next iteration overwrites

        // residual into GC branch
        o1.x += x4.x; o1.y += x4.y; o1.z += x4.z; o1.w += x4.w;
        // leaky relu (slope 0.2)
        o1.x = o1.x > 0.f ? o1.x : 0.2f * o1.x;
        o1.y = o1.y > 0.f ? o1.y : 0.2f * o1.y;
        o1.z = o1.z > 0.f ? o1.z : 0.2f * o1.z;
        o1.w = o1.w > 0.f ? o1.w : 0.2f * o1.w;
        o2.x = o2.x > 0.f ? o2.x : 0.2f * o2.x;
        o2.y = o2.y > 0.f ? o2.y : 0.2f * o2.y;
        o2.z = o2.z > 0.f ? o2.z : 0.2f * o2.z;
        o2.w = o2.w > 0.f ? o2.w : 0.2f * o2.w;

        float4 nv = make_float4(o1.x + o2.x, o1.y + o2.y, o1.z + o2.z, o1.w + o2.w);
        float ss = nv.x * nv.x + nv.y * nv.y + nv.z * nv.z + nv.w * nv.w;
#pragma unroll
        for (int off = 8; off > 0; off >>= 1)
            ss += __shfl_xor_sync(0xffffffffu, ss, off);
        float r = 1.0f / fmaxf(sqrtf(ss), 1e-12f);
        nv.x *= r; nv.y *= r; nv.z *= r; nv.w *= r;

        ((float4*)g_all)[v * 16 + c] = nv;

        float4 o = ((float4*)out)[v * 16 + c];
        o.x += nv.x; o.y += nv.y; o.z += nv.z; o.w += nv.w;
        if (finalize) { o.x *= 0.25f; o.y *= 0.25f; o.z *= 0.25f; o.w *= 0.25f; }
        ((float4*)out)[v * 16 + c] = o;
    }
}

// ---------------- launch ------------------------------------------------------
extern "C" void kernel_launch(void* const* d_in, const int* in_sizes, int n_in,
                              void* d_out, int out_size) {
    const float* u_emb = (const float*)d_in[0];
    const float* i_emb = (const float*)d_in[1];
    const float* Wgc   = (const float*)d_in[2];
    const float* bgc   = (const float*)d_in[3];
    const float* Wbi   = (const float*)d_in[4];
    const float* bbi   = (const float*)d_in[5];
    const int*   eu    = (const int*)d_in[6];
    const int*   ei    = (const int*)d_in[7];
    float* out = (float*)d_out;

    const int VB = (NV + 255) / 256;
    const int EB = (NE + 255) / 256;
    const int RB = NV * 16 / 256;  // 9375, exact

    zero_deg_kernel<<<VB, 256>>>();
    deg_kernel<<<EB, 256>>>(eu, ei);
    scales_kernel<<<VB, 256>>>();
    scan_kernel<<<1, 1024>>>();
    scatter_kernel<<<EB, 256>>>(eu, ei);
    init_kernel<<<RB, 256>>>((const float4*)u_emb, (const float4*)i_emb, (float4*)out);

    for (int l = 0; l < 3; ++l) {
        gather_kernel<0><<<RB, 256>>>();
        gather_kernel<1><<<RB, 256>>>();
        transform_kernel<<<1184, 256>>>(Wgc, bgc, Wbi, bbi, out, l, l == 2 ? 1 : 0);
    }
}

// round 3
// speedup vs baseline: 1.2139x; 1.2139x over previous
#include <cuda_runtime.h>

#define NUSR 100000
#define NITM 50000
#define NV   150000
#define NE   1000000
#define DIM  64

// ---------------- scratch (static device globals; no allocation) -------------
__device__ float g_all[(size_t)NV * DIM];   // current embeddings (users, then items)
__device__ float g_ef [(size_t)NV * DIM];   // stage-A result
__device__ float g_y  [(size_t)NV * DIM];   // stage-B result
__device__ int   g_deg[NV];
__device__ float g_isq[NV];                 // deg^-1/2 (0 if deg==0)
__device__ float g_inv[NV];                 // deg^-1   (0 if deg==0)
__device__ int   g_rs [NV];                 // CSR row starts (contiguous, NOT monotone)
__device__ int   g_cur[NV];                 // scatter cursors
__device__ int   g_col[2 * NE];             // CSR columns (global vertex ids)
__device__ int   g_total;                   // running base for row-range assignment

// ---------------- CSR build ---------------------------------------------------
__global__ void zero_deg_kernel() {
    int v = blockIdx.x * blockDim.x + threadIdx.x;
    if (v < NV) g_deg[v] = 0;
    if (v == 0) g_total = 0;
}

__global__ void deg_kernel(const int* __restrict__ eu, const int* __restrict__ ei) {
    int e = blockIdx.x * blockDim.x + threadIdx.x;
    if (e < NE) {
        atomicAdd(&g_deg[eu[e]], 1);
        atomicAdd(&g_deg[NUSR + ei[e]], 1);
    }
}

// Per-block: scales + intra-block exclusive scan + one global atomic for base.
// Row ranges are contiguous but in arbitrary global order — gather uses
// [rs[v], rs[v]+deg[v]), so monotonicity is not required.
__global__ __launch_bounds__(256) void offsets_kernel() {
    __shared__ int sh[256];
    __shared__ int base;
    int t = threadIdx.x;
    int v = blockIdx.x * 256 + t;
    int d = (v < NV) ? g_deg[v] : 0;

    if (v < NV) {
        if (d > 0) {
            float fd = (float)d;
            g_isq[v] = rsqrtf(fd);
            g_inv[v] = 1.0f / fd;
        } else {
            g_isq[v] = 0.0f;
            g_inv[v] = 0.0f;
        }
    }

    sh[t] = d;
    __syncthreads();
#pragma unroll
    for (int off = 1; off < 256; off <<= 1) {
        int x = sh[t];
        int add = (t >= off) ? sh[t - off] : 0;
        __syncthreads();
        sh[t] = x + add;
        __syncthreads();
    }
    int incl = sh[t];
    if (t == 255) base = atomicAdd(&g_total, incl);
    __syncthreads();

    if (v < NV) {
        int beg = base + incl - d;  // exclusive within block + block base
        g_rs[v]  = beg;
        g_cur[v] = beg;
    }
}

__global__ void scatter_kernel(const int* __restrict__ eu, const int* __restrict__ ei) {
    int e = blockIdx.x * blockDim.x + threadIdx.x;
    if (e < NE) {
        int u = eu[e];
        int i = NUSR + ei[e];
        int p = atomicAdd(&g_cur[u], 1);
        g_col[p] = i;
        int q = atomicAdd(&g_cur[i], 1);
        g_col[q] = u;
    }
}

// ---------------- init: all_embs = concat(u,i); out (mean-accumulator) = same -
__global__ void init_kernel(const float4* __restrict__ ue,
                            const float4* __restrict__ ie,
                            float4* __restrict__ out) {
    int n = blockIdx.x * blockDim.x + threadIdx.x;  // < NV*16
    float4 v = (n < NUSR * 16) ? ue[n] : ie[n - NUSR * 16];
    ((float4*)g_all)[n] = v;
    out[n] = v;
}

// ---------------- gather stages ----------------------------------------------
// STAGE 0 (scaled):   g_ef[v] = inv[v] * sum_{w in N(v)} g_all[w]*isq[w]
// STAGE 1 (unscaled): g_y[v]  =          sum_{w in N(v)} g_ef[w]
template <int STAGE>
__global__ void gather_kernel() {
    int gid = blockIdx.x * blockDim.x + threadIdx.x;  // NV*16 threads
    int v = gid >> 4;
    int c = gid & 15;
    const float4* __restrict__ src =
        (STAGE == 0) ? (const float4*)g_all : (const float4*)g_ef;
    int beg = g_rs[v];
    int end = beg + g_deg[v];
    float4 acc = make_float4(0.f, 0.f, 0.f, 0.f);
    int n = beg;
    for (; n + 4 <= end; n += 4) {
        int w0 = g_col[n + 0], w1 = g_col[n + 1], w2 = g_col[n + 2], w3 = g_col[n + 3];
        float4 a = src[w0 * 16 + c];
        float4 b = src[w1 * 16 + c];
        float4 d2 = src[w2 * 16 + c];
        float4 d3 = src[w3 * 16 + c];
        if (STAGE == 0) {
            float s0 = g_isq[w0], s1 = g_isq[w1], s2 = g_isq[w2], s3 = g_isq[w3];
            acc.x = fmaf(a.x, s0, acc.x); acc.y = fmaf(a.y, s0, acc.y);
            acc.z = fmaf(a.z, s0, acc.z); acc.w = fmaf(a.w, s0, acc.w);
            acc.x = fmaf(b.x, s1, acc.x); acc.y = fmaf(b.y, s1, acc.y);
            acc.z = fmaf(b.z, s1, acc.z); acc.w = fmaf(b.w, s1, acc.w);
            acc.x = fmaf(d2.x, s2, acc.x); acc.y = fmaf(d2.y, s2, acc.y);
            acc.z = fmaf(d2.z, s2, acc.z); acc.w = fmaf(d2.w, s2, acc.w);
            acc.x = fmaf(d3.x, s3, acc.x); acc.y = fmaf(d3.y, s3, acc.y);
            acc.z = fmaf(d3.z, s3, acc.z); acc.w = fmaf(d3.w, s3, acc.w);
        } else {
            acc.x += a.x + b.x + d2.x + d3.x;
            acc.y += a.y + b.y + d2.y + d3.y;
            acc.z += a.z + b.z + d2.z + d3.z;
            acc.w += a.w + b.w + d2.w + d3.w;
        }
    }
    for (; n < end; ++n) {
        int w = g_col[n];
        float4 a = src[w * 16 + c];
        float s = (STAGE == 0) ? g_isq[w] : 1.0f;
        acc.x = fmaf(a.x, s, acc.x);
        acc.y = fmaf(a.y, s, acc.y);
        acc.z = fmaf(a.z, s, acc.z);
        acc.w = fmaf(a.w, s, acc.w);
    }
    if (STAGE == 0) {
        float iv = g_inv[v];
        acc.x *= iv; acc.y *= iv; acc.z *= iv; acc.w *= iv;
        ((float4*)g_ef)[v * 16 + c] = acc;
    } else {
        ((float4*)g_y)[v * 16 + c] = acc;
    }
}

// ---------------- fused dense transform --------------------------------------
// g = Y[v]*isq[v]; x = all[v]
// o1 = leaky( Wgc g + bgc + x ), o2 = leaky( Wbi (x*g) + bbi )
// nv = (o1+o2) / max(||o1+o2||, 1e-12);  all[v]=nv;  out[v]+=nv (finalize: *0.25)
__global__ __launch_bounds__(256) void transform_kernel(
    const float* __restrict__ Wgc, const float* __restrict__ bgc,
    const float* __restrict__ Wbi, const float* __restrict__ bbi,
    float* __restrict__ out, int l, int finalize) {
    __shared__ float sWg[64 * 64];   // transposed: sWg[k*64+j] = Wgc[l][j][k]
    __shared__ float sWb[64 * 64];
    __shared__ float sG[16 * 64];
    __shared__ float sH[16 * 64];
    __shared__ float sbg[64], sbb[64];

    const float* Wg = Wgc + l * 4096;
    const float* Wb = Wbi + l * 4096;
    for (int idx = threadIdx.x; idx < 4096; idx += 256) {
        int j = idx >> 6, k = idx & 63;
        sWg[k * 64 + j] = Wg[idx];
        sWb[k * 64 + j] = Wb[idx];
    }
    if (threadIdx.x < 64) {
        sbg[threadIdx.x] = bgc[l * 64 + threadIdx.x];
        sbb[threadIdx.x] = bbi[l * 64 + threadIdx.x];
    }
    __syncthreads();

    int grp = threadIdx.x >> 4;   // vertex slot 0..15 (2 per warp)
    int c   = threadIdx.x & 15;   // float4 chunk -> outputs j = 4c..4c+3
    float* gb = sG + grp * 64;
    float* hb = sH + grp * 64;

    // NV % 16 == 0 and v0 is a multiple of 16, so every lane's v is valid
    for (int v0 = blockIdx.x * 16; v0 < NV; v0 += gridDim.x * 16) {
        int v = v0 + grp;
        float s = g_isq[v];
        float4 y4 = ((const float4*)g_y)[v * 16 + c];
        float4 x4 = ((const float4*)g_all)[v * 16 + c];
        float4 g4 = make_float4(y4.x * s, y4.y * s, y4.z * s, y4.w * s);
        float4 h4 = make_float4(g4.x * x4.x, g4.y * x4.y, g4.z * x4.z, g4.w * x4.w);
        ((float4*)gb)[c] = g4;
        ((float4*)hb)[c] = h4;
        __syncwarp();

        float4 o1 = *(const float4*)(sbg + 4 * c);
        float4 o2 = *(const float4*)(sbb + 4 * c);
#pragma unroll
        for (int k = 0; k < 64; k += 4) {
            float4 gk = *(const float4*)(gb + k);
            float4 hk = *(const float4*)(hb + k);
            {
                float4 wa = *(const float4*)(sWg + (k + 0) * 64 + 4 * c);
                float4 wbv = *(const float4*)(sWb + (k + 0) * 64 + 4 * c);
                o1.x = fmaf(gk.x, wa.x, o1.x); o1.y = fmaf(gk.x, wa.y, o1.y);
                o1.z = fmaf(gk.x, wa.z, o1.z); o1.w = fmaf(gk.x, wa.w, o1.w);
                o2.x = fmaf(hk.x, wbv.x, o2.x); o2.y = fmaf(hk.x, wbv.y, o2.y);
                o2.z = fmaf(hk.x, wbv.z, o2.z); o2.w = fmaf(hk.x, wbv.w, o2.w);
            }
            {
                float4 wa = *(const float4*)(sWg + (k + 1) * 64 + 4 * c);
                float4 wbv = *(const float4*)(sWb + (k + 1) * 64 + 4 * c);
                o1.x = fmaf(gk.y, wa.x, o1.x); o1.y = fmaf(gk.y, wa.y, o1.y);
                o1.z = fmaf(gk.y, wa.z, o1.z); o1.w = fmaf(gk.y, wa.w, o1.w);
                o2.x = fmaf(hk.y, wbv.x, o2.x); o2.y = fmaf(hk.y, wbv.y, o2.y);
                o2.z = fmaf(hk.y, wbv.z, o2.z); o2.w = fmaf(hk.y, wbv.w, o2.w);
            }
            {
                float4 wa = *(const float4*)(sWg + (k + 2) * 64 + 4 * c);
                float4 wbv = *(const float4*)(sWb + (k + 2) * 64 + 4 * c);
                o1.x = fmaf(gk.z, wa.x, o1.x); o1.y = fmaf(gk.z, wa.y, o1.y);
                o1.z = fmaf(gk.z, wa.z, o1.z); o1.w = fmaf(gk.z, wa.w, o1.w);
                o2.x = fmaf(hk.z, wbv.x, o2.x); o2.y = fmaf(hk.z, wbv.y, o2.y);
                o2.z = fmaf(hk.z, wbv.z, o2.z); o2.w = fmaf(hk.z, wbv.w, o2.w);
            }
            {
                float4 wa = *(const float4*)(sWg + (k + 3) * 64 + 4 * c);
                float4 wbv = *(const float4*)(sWb + (k + 3) * 64 + 4 * c);
                o1.x = fmaf(gk.w, wa.x, o1.x); o1.y = fmaf(gk.w, wa.y, o1.y);
                o1.z = fmaf(gk.w, wa.z, o1.z); o1.w = fmaf(gk.w, wa.w, o1.w);
                o2.x = fmaf(hk.w, wbv.x, o2.x); o2.y = fmaf(hk.w, wbv.y, o2.y);
                o2.z = fmaf(hk.w, wbv.z, o2.z); o2.w = fmaf(hk.w, wbv.w, o2.w);
            }
        }
        __syncwarp();  // matvec reads of sG/sH complete before next iteration overwrites

        // residual into GC branch
        o1.x += x4.x; o1.y += x4.y; o1.z += x4.z; o1.w += x4.w;
        // leaky relu (slope 0.2)
        o1.x = o1.x > 0.f ? o1.x : 0.2f * o1.x;
        o1.y = o1.y > 0.f ? o1.y : 0.2f * o1.y;
        o1.z = o1.z > 0.f ? o1.z : 0.2f * o1.z;
        o1.w = o1.w > 0.f ? o1.w : 0.2f * o1.w;
        o2.x = o2.x > 0.f ? o2.x : 0.2f * o2.x;
        o2.y = o2.y > 0.f ? o2.y : 0.2f * o2.y;
        o2.z = o2.z > 0.f ? o2.z : 0.2f * o2.z;
        o2.w = o2.w > 0.f ? o2.w : 0.2f * o2.w;

        float4 nv = make_float4(o1.x + o2.x, o1.y + o2.y, o1.z + o2.z, o1.w + o2.w);
        float ss = nv.x * nv.x + nv.y * nv.y + nv.z * nv.z + nv.w * nv.w;
#pragma unroll
        for (int off = 8; off > 0; off >>= 1)
            ss += __shfl_xor_sync(0xffffffffu, ss, off);
        float r = 1.0f / fmaxf(sqrtf(ss), 1e-12f);
        nv.x *= r; nv.y *= r; nv.z *= r; nv.w *= r;

        ((float4*)g_all)[v * 16 + c] = nv;

        float4 o = ((float4*)out)[v * 16 + c];
        o.x += nv.x; o.y += nv.y; o.z += nv.z; o.w += nv.w;
        if (finalize) { o.x *= 0.25f; o.y *= 0.25f; o.z *= 0.25f; o.w *= 0.25f; }
        ((float4*)out)[v * 16 + c] = o;
    }
}

// ---------------- launch ------------------------------------------------------
extern "C" void kernel_launch(void* const* d_in, const int* in_sizes, int n_in,
                              void* d_out, int out_size) {
    const float* u_emb = (const float*)d_in[0];
    const float* i_emb = (const float*)d_in[1];
    const float* Wgc   = (const float*)d_in[2];
    const float* bgc   = (const float*)d_in[3];
    const float* Wbi   = (const float*)d_in[4];
    const float* bbi   = (const float*)d_in[5];
    const int*   eu    = (const int*)d_in[6];
    const int*   ei    = (const int*)d_in[7];
    float* out = (float*)d_out;

    const int VB = (NV + 255) / 256;
    const int EB = (NE + 255) / 256;
    const int RB = NV * 16 / 256;  // 9375, exact

    zero_deg_kernel<<<VB, 256>>>();
    deg_kernel<<<EB, 256>>>(eu, ei);
    offsets_kernel<<<VB, 256>>>();
    scatter_kernel<<<EB, 256>>>(eu, ei);
    init_kernel<<<RB, 256>>>((const float4*)u_emb, (const float4*)i_emb, (float4*)out);

    for (int l = 0; l < 3; ++l) {
        gather_kernel<0><<<RB, 256>>>();
        gather_kernel<1><<<RB, 256>>>();
        transform_kernel<<<1184, 256>>>(Wgc, bgc, Wbi, bbi, out, l, l == 2 ? 1 : 0);
    }
}

// round 4
// speedup vs baseline: 1.3435x; 1.1068x over previous
#include <cuda_runtime.h>

#define NUSR 100000
#define NITM 50000
#define NV   150000
#define NVP  150016          // padded to a multiple of 64 for the transform tile
#define NE   1000000
#define DIM  64

// ---------------- scratch (static device globals; no allocation) -------------
// Padding region [NV, NVP) of these arrays is either never written (stays 0
// from .bss init: g_y, g_isq, g_inv) or written deterministically (g_all,
// g_ef), so replays are deterministic.
__device__ float g_all[(size_t)NVP * DIM];
__device__ float g_ef [(size_t)NVP * DIM];
__device__ float g_y  [(size_t)NVP * DIM];
__device__ int   g_deg[NV];
__device__ float g_isq[NVP];
__device__ float g_inv[NVP];
__device__ int   g_rs [NV];                 // CSR row starts (contiguous, NOT monotone)
__device__ int   g_cur[NV];
__device__ int   g_col[2 * NE];
__device__ int   g_total;

// ---------------- CSR build ---------------------------------------------------
__global__ void zero_deg_kernel() {
    int v = blockIdx.x * blockDim.x + threadIdx.x;
    if (v < NV) g_deg[v] = 0;
    if (v == 0) g_total = 0;
}

__global__ void deg_kernel(const int* __restrict__ eu, const int* __restrict__ ei) {
    int e = blockIdx.x * blockDim.x + threadIdx.x;
    if (e < NE) {
        atomicAdd(&g_deg[eu[e]], 1);
        atomicAdd(&g_deg[NUSR + ei[e]], 1);
    }
}

// Per-block: scales + intra-block exclusive scan + one global atomic for base.
__global__ __launch_bounds__(256) void offsets_kernel() {
    __shared__ int sh[256];
    __shared__ int base;
    int t = threadIdx.x;
    int v = blockIdx.x * 256 + t;
    int d = (v < NV) ? g_deg[v] : 0;

    if (v < NV) {
        if (d > 0) {
            float fd = (float)d;
            g_isq[v] = rsqrtf(fd);
            g_inv[v] = 1.0f / fd;
        } else {
            g_isq[v] = 0.0f;
            g_inv[v] = 0.0f;
        }
    }

    sh[t] = d;
    __syncthreads();
#pragma unroll
    for (int off = 1; off < 256; off <<= 1) {
        int x = sh[t];
        int add = (t >= off) ? sh[t - off] : 0;
        __syncthreads();
        sh[t] = x + add;
        __syncthreads();
    }
    int incl = sh[t];
    if (t == 255) base = atomicAdd(&g_total, incl);
    __syncthreads();

    if (v < NV) {
        int beg = base + incl - d;
        g_rs[v]  = beg;
        g_cur[v] = beg;
    }
}

__global__ void scatter_kernel(const int* __restrict__ eu, const int* __restrict__ ei) {
    int e = blockIdx.x * blockDim.x + threadIdx.x;
    if (e < NE) {
        int u = eu[e];
        int i = NUSR + ei[e];
        int p = atomicAdd(&g_cur[u], 1);
        g_col[p] = i;
        int q = atomicAdd(&g_cur[i], 1);
        g_col[q] = u;
    }
}

// ---------------- init -------------------------------------------------------
__global__ void init_kernel(const float4* __restrict__ ue,
                            const float4* __restrict__ ie,
                            float4* __restrict__ out) {
    int n = blockIdx.x * blockDim.x + threadIdx.x;  // < NV*16
    float4 v = (n < NUSR * 16) ? ue[n] : ie[n - NUSR * 16];
    ((float4*)g_all)[n] = v;
    out[n] = v;
}

// ---------------- gather stages: one WARP per vertex -------------------------
// STAGE 0: g_ef[v] = inv[v] * sum_{w in N(v)} g_all[w]*isq[w]
// STAGE 1: g_y[v]  =          sum_{w in N(v)} g_ef[w]
// 32 lanes each own one float2 chunk; trip count uniform across the warp;
// g_col loads are warp-uniform broadcasts.
template <int STAGE>
__global__ __launch_bounds__(256) void gather_kernel() {
    int gid  = blockIdx.x * blockDim.x + threadIdx.x;   // NV*32 threads
    int v    = gid >> 5;
    int lane = gid & 31;
    const float2* __restrict__ src =
        (STAGE == 0) ? (const float2*)g_all : (const float2*)g_ef;
    int beg = g_rs[v];
    int end = beg + g_deg[v];
    float2 acc = make_float2(0.f, 0.f);
    int n = beg;
    for (; n + 4 <= end; n += 4) {
        int w0 = g_col[n + 0], w1 = g_col[n + 1], w2 = g_col[n + 2], w3 = g_col[n + 3];
        float2 a0 = src[w0 * 32 + lane];
        float2 a1 = src[w1 * 32 + lane];
        float2 a2 = src[w2 * 32 + lane];
        float2 a3 = src[w3 * 32 + lane];
        if (STAGE == 0) {
            float s0 = g_isq[w0], s1 = g_isq[w1], s2 = g_isq[w2], s3 = g_isq[w3];
            acc.x = fmaf(a0.x, s0, acc.x); acc.y = fmaf(a0.y, s0, acc.y);
            acc.x = fmaf(a1.x, s1, acc.x); acc.y = fmaf(a1.y, s1, acc.y);
            acc.x = fmaf(a2.x, s2, acc.x); acc.y = fmaf(a2.y, s2, acc.y);
            acc.x = fmaf(a3.x, s3, acc.x); acc.y = fmaf(a3.y, s3, acc.y);
        } else {
            acc.x += (a0.x + a1.x) + (a2.x + a3.x);
            acc.y += (a0.y + a1.y) + (a2.y + a3.y);
        }
    }
    for (; n < end; ++n) {
        int w = g_col[n];
        float2 a = src[w * 32 + lane];
        if (STAGE == 0) {
            float s = g_isq[w];
            acc.x = fmaf(a.x, s, acc.x);
            acc.y = fmaf(a.y, s, acc.y);
        } else {
            acc.x += a.x;
            acc.y += a.y;
        }
    }
    if (STAGE == 0) {
        float iv = g_inv[v];
        acc.x *= iv; acc.y *= iv;
        ((float2*)g_ef)[v * 32 + lane] = acc;
    } else {
        ((float2*)g_y)[v * 32 + lane] = acc;
    }
}

// ---------------- fused dense transform, 4 vertices per thread ---------------
// Each 16-lane group handles 4 vertices; each block handles 64 vertices.
// Weight smem loads are amortized over 4 vertices -> LDS/FMA balanced.
__global__ __launch_bounds__(256) void transform_kernel(
    const float* __restrict__ Wgc, const float* __restrict__ bgc,
    const float* __restrict__ Wbi, const float* __restrict__ bbi,
    float* __restrict__ out, int l, int finalize) {
    __shared__ float sWg[64 * 64];   // transposed: sWg[k*64+j] = Wgc[l][j][k]
    __shared__ float sWb[64 * 64];
    __shared__ float sG[64 * 64];    // 64 vertices x 64 dims
    __shared__ float sH[64 * 64];
    __shared__ float sbg[64], sbb[64];

    const float* Wg = Wgc + l * 4096;
    const float* Wb = Wbi + l * 4096;
    for (int idx = threadIdx.x; idx < 4096; idx += 256) {
        int j = idx >> 6, k = idx & 63;
        sWg[k * 64 + j] = Wg[idx];
        sWb[k * 64 + j] = Wb[idx];
    }
    if (threadIdx.x < 64) {
        sbg[threadIdx.x] = bgc[l * 64 + threadIdx.x];
        sbb[threadIdx.x] = bbi[l * 64 + threadIdx.x];
    }
    __syncthreads();

    int grp = threadIdx.x >> 4;   // 16 groups of 16 lanes
    int c   = threadIdx.x & 15;   // output float4 chunk j = 4c..4c+3

    int vb = blockIdx.x * 64 + grp * 4;   // first of this group's 4 vertices (< NVP)

    float4 x4[4];
    // stage g = y*isq and h = x*g for the 4 vertices
#pragma unroll
    for (int u = 0; u < 4; ++u) {
        int v = vb + u;
        float s = g_isq[v];
        float4 y4 = ((const float4*)g_y)[v * 16 + c];
        x4[u] = ((const float4*)g_all)[v * 16 + c];
        float4 g4 = make_float4(y4.x * s, y4.y * s, y4.z * s, y4.w * s);
        float4 h4 = make_float4(g4.x * x4[u].x, g4.y * x4[u].y,
                                g4.z * x4[u].z, g4.w * x4[u].w);
        ((float4*)(sG + (grp * 4 + u) * 64))[c] = g4;
        ((float4*)(sH + (grp * 4 + u) * 64))[c] = h4;
    }
    __syncwarp();

    float4 o1[4], o2[4];
    {
        float4 bg = *(const float4*)(sbg + 4 * c);
        float4 bb = *(const float4*)(sbb + 4 * c);
#pragma unroll
        for (int u = 0; u < 4; ++u) { o1[u] = bg; o2[u] = bb; }
    }

#pragma unroll
    for (int k = 0; k < 64; k += 4) {
        float4 wa0 = *(const float4*)(sWg + (k + 0) * 64 + 4 * c);
        float4 wa1 = *(const float4*)(sWg + (k + 1) * 64 + 4 * c);
        float4 wa2 = *(const float4*)(sWg + (k + 2) * 64 + 4 * c);
        float4 wa3 = *(const float4*)(sWg + (k + 3) * 64 + 4 * c);
        float4 wb0 = *(const float4*)(sWb + (k + 0) * 64 + 4 * c);
        float4 wb1 = *(const float4*)(sWb + (k + 1) * 64 + 4 * c);
        float4 wb2 = *(const float4*)(sWb + (k + 2) * 64 + 4 * c);
        float4 wb3 = *(const float4*)(sWb + (k + 3) * 64 + 4 * c);
#pragma unroll
        for (int u = 0; u < 4; ++u) {
            const float* gb = sG + (grp * 4 + u) * 64;
            const float* hb = sH + (grp * 4 + u) * 64;
            float4 gk = *(const float4*)(gb + k);
            float4 hk = *(const float4*)(hb + k);
            o1[u].x = fmaf(gk.x, wa0.x, o1[u].x); o1[u].y = fmaf(gk.x, wa0.y, o1[u].y);
            o1[u].z = fmaf(gk.x, wa0.z, o1[u].z); o1[u].w = fmaf(gk.x, wa0.w, o1[u].w);
            o1[u].x = fmaf(gk.y, wa1.x, o1[u].x); o1[u].y = fmaf(gk.y, wa1.y, o1[u].y);
            o1[u].z = fmaf(gk.y, wa1.z, o1[u].z); o1[u].w = fmaf(gk.y, wa1.w, o1[u].w);
            o1[u].x = fmaf(gk.z, wa2.x, o1[u].x); o1[u].y = fmaf(gk.z, wa2.y, o1[u].y);
            o1[u].z = fmaf(gk.z, wa2.z, o1[u].z); o1[u].w = fmaf(gk.z, wa2.w, o1[u].w);
            o1[u].x = fmaf(gk.w, wa3.x, o1[u].x); o1[u].y = fmaf(gk.w, wa3.y, o1[u].y);
            o1[u].z = fmaf(gk.w, wa3.z, o1[u].z); o1[u].w = fmaf(gk.w, wa3.w, o1[u].w);
            o2[u].x = fmaf(hk.x, wb0.x, o2[u].x); o2[u].y = fmaf(hk.x, wb0.y, o2[u].y);
            o2[u].z = fmaf(hk.x, wb0.z, o2[u].z); o2[u].w = fmaf(hk.x, wb0.w, o2[u].w);
            o2[u].x = fmaf(hk.y, wb1.x, o2[u].x); o2[u].y = fmaf(hk.y, wb1.y, o2[u].y);
            o2[u].z = fmaf(hk.y, wb1.z, o2[u].z); o2[u].w = fmaf(hk.y, wb1.w, o2[u].w);
            o2[u].x = fmaf(hk.z, wb2.x, o2[u].x); o2[u].y = fmaf(hk.z, wb2.y, o2[u].y);
            o2[u].z = fmaf(hk.z, wb2.z, o2[u].z); o2[u].w = fmaf(hk.z, wb2.w, o2[u].w);
            o2[u].x = fmaf(hk.w, wb3.x, o2[u].x); o2[u].y = fmaf(hk.w, wb3.y, o2[u].y);
            o2[u].z = fmaf(hk.w, wb3.z, o2[u].z); o2[u].w = fmaf(hk.w, wb3.w, o2[u].w);
        }
    }

#pragma unroll
    for (int u = 0; u < 4; ++u) {
        int v = vb + u;
        float4 a = o1[u], b = o2[u];
        a.x += x4[u].x; a.y += x4[u].y; a.z += x4[u].z; a.w += x4[u].w;
        a.x = a.x > 0.f ? a.x : 0.2f * a.x;
        a.y = a.y > 0.f ? a.y : 0.2f * a.y;
        a.z = a.z > 0.f ? a.z : 0.2f * a.z;
        a.w = a.w > 0.f ? a.w : 0.2f * a.w;
        b.x = b.x > 0.f ? b.x : 0.2f * b.x;
        b.y = b.y > 0.f ? b.y : 0.2f * b.y;
        b.z = b.z > 0.f ? b.z : 0.2f * b.z;
        b.w = b.w > 0.f ? b.w : 0.2f * b.w;
        float4 nv = make_float4(a.x + b.x, a.y + b.y, a.z + b.z, a.w + b.w);
        float ss = nv.x * nv.x + nv.y * nv.y + nv.z * nv.z + nv.w * nv.w;
#pragma unroll
        for (int off = 8; off > 0; off >>= 1)
            ss += __shfl_xor_sync(0xffffffffu, ss, off);
        float r = 1.0f / fmaxf(sqrtf(ss), 1e-12f);
        nv.x *= r; nv.y *= r; nv.z *= r; nv.w *= r;

        ((float4*)g_all)[v * 16 + c] = nv;

        if (v < NV) {
            float4 o = ((float4*)out)[v * 16 + c];
            o.x += nv.x; o.y += nv.y; o.z += nv.z; o.w += nv.w;
            if (finalize) { o.x *= 0.25f; o.y *= 0.25f; o.z *= 0.25f; o.w *= 0.25f; }
            ((float4*)out)[v * 16 + c] = o;
        }
    }
}

// ---------------- launch ------------------------------------------------------
extern "C" void kernel_launch(void* const* d_in, const int* in_sizes, int n_in,
                              void* d_out, int out_size) {
    const float* u_emb = (const float*)d_in[0];
    const float* i_emb = (const float*)d_in[1];
    const float* Wgc   = (const float*)d_in[2];
    const float* bgc   = (const float*)d_in[3];
    const float* Wbi   = (const float*)d_in[4];
    const float* bbi   = (const float*)d_in[5];
    const int*   eu    = (const int*)d_in[6];
    const int*   ei    = (const int*)d_in[7];
    float* out = (float*)d_out;

    const int VB = (NV + 255) / 256;
    const int EB = (NE + 255) / 256;
    const int IB = NV * 16 / 256;    // init: 9375 exact
    const int GB = NV * 32 / 256;    // gather: 18750 exact
    const int TB = NVP / 64;         // transform: 2344 exact (padded)

    zero_deg_kernel<<<VB, 256>>>();
    deg_kernel<<<EB, 256>>>(eu, ei);
    offsets_kernel<<<VB, 256>>>();
    scatter_kernel<<<EB, 256>>>(eu, ei);
    init_kernel<<<IB, 256>>>((const float4*)u_emb, (const float4*)i_emb, (float4*)out);

    for (int l = 0; l < 3; ++l) {
        gather_kernel<0><<<GB, 256>>>();
        gather_kernel<1><<<GB, 256>>>();
        transform_kernel<<<TB, 256>>>(Wgc, bgc, Wbi, bbi, out, l, l == 2 ? 1 : 0);
    }
}

// round 16
// speedup vs baseline: 1.3718x; 1.0211x over previous
#include <cuda_runtime.h>
#include <cuda_fp16.h>

#define NUSR 100000
#define NITM 50000
#define NV   150000
#define NVP  150016          // padded to a multiple of 64 for the transform tile
#define NE   1000000
#define DIM  64

// ---------------- scratch (static device globals; no allocation) -------------
// Padding region [NV, NVP): g_y/g_isq/g_inv never written (stay 0 from .bss);
// g_all/g_allh written deterministically by transform -> replays deterministic.
__device__ float  g_all [(size_t)NVP * DIM];   // fp32 embeddings
__device__ __half g_allh[(size_t)NVP * DIM];   // fp16 copy, PRE-SCALED by isq[v]
__device__ __half g_efh [(size_t)NV  * DIM];   // stage-A result EF (fp16)
__device__ float  g_y   [(size_t)NVP * DIM];   // stage-B result (fp32)
__device__ int    g_deg[NV];
__device__ float  g_isq[NVP];
__device__ float  g_inv[NVP];
__device__ int    g_rs [NV];                   // CSR row starts (contiguous, NOT monotone)
__device__ int    g_cur[NV];
__device__ int    g_col[2 * NE];
__device__ int    g_total;

// ---------------- CSR build ---------------------------------------------------
__global__ void zero_deg_kernel() {
    int v = blockIdx.x * blockDim.x + threadIdx.x;
    if (v < NV) g_deg[v] = 0;
    if (v == 0) g_total = 0;
}

__global__ void deg_kernel(const int* __restrict__ eu, const int* __restrict__ ei) {
    int e = blockIdx.x * blockDim.x + threadIdx.x;
    if (e < NE) {
        atomicAdd(&g_deg[eu[e]], 1);
        atomicAdd(&g_deg[NUSR + ei[e]], 1);
    }
}

// Per-block: scales + intra-block exclusive scan + one global atomic for base.
__global__ __launch_bounds__(256) void offsets_kernel() {
    __shared__ int sh[256];
    __shared__ int base;
    int t = threadIdx.x;
    int v = blockIdx.x * 256 + t;
    int d = (v < NV) ? g_deg[v] : 0;

    if (v < NV) {
        if (d > 0) {
            float fd = (float)d;
            g_isq[v] = rsqrtf(fd);
            g_inv[v] = 1.0f / fd;
        } else {
            g_isq[v] = 0.0f;
            g_inv[v] = 0.0f;
        }
    }

    sh[t] = d;
    __syncthreads();
#pragma unroll
    for (int off = 1; off < 256; off <<= 1) {
        int x = sh[t];
        int add = (t >= off) ? sh[t - off] : 0;
        __syncthreads();
        sh[t] = x + add;
        __syncthreads();
    }
    int incl = sh[t];
    if (t == 255) base = atomicAdd(&g_total, incl);
    __syncthreads();

    if (v < NV) {
        int beg = base + incl - d;
        g_rs[v]  = beg;
        g_cur[v] = beg;
    }
}

__global__ void scatter_kernel(const int* __restrict__ eu, const int* __restrict__ ei) {
    int e = blockIdx.x * blockDim.x + threadIdx.x;
    if (e < NE) {
        int u = eu[e];
        int i = NUSR + ei[e];
        int p = atomicAdd(&g_cur[u], 1);
        g_col[p] = i;
        int q = atomicAdd(&g_cur[i], 1);
        g_col[q] = u;
    }
}

// ---------------- init (after offsets: needs isq) ----------------------------
__global__ void init_kernel(const float4* __restrict__ ue,
                            const float4* __restrict__ ie,
                            float4* __restrict__ out) {
    int n = blockIdx.x * blockDim.x + threadIdx.x;  // < NV*16
    float4 v = (n < NUSR * 16) ? ue[n] : ie[n - NUSR * 16];
    ((float4*)g_all)[n] = v;
    out[n] = v;
    float s = g_isq[n >> 4];
    ((__half2*)g_allh)[2 * n + 0] = __floats2half2_rn(v.x * s, v.y * s);
    ((__half2*)g_allh)[2 * n + 1] = __floats2half2_rn(v.z * s, v.w * s);
}

// ---------------- gather stages: one WARP per vertex, fp16 rows --------------
// STAGE 0: EF[v] = inv[v] * sum_{w in N(v)} allh[w]      (allh pre-scaled by isq)
// STAGE 1: Y[v]  =          sum_{w in N(v)} EF[w]
template <int STAGE>
__global__ __launch_bounds__(256) void gather_kernel() {
    int gid  = blockIdx.x * blockDim.x + threadIdx.x;   // NV*32 threads
    int v    = gid >> 5;
    int lane = gid & 31;
    const __half2* __restrict__ src =
        (STAGE == 0) ? (const __half2*)g_allh : (const __half2*)g_efh;
    int beg = g_rs[v];
    int end = beg + g_deg[v];
    float2 acc = make_float2(0.f, 0.f);
    int n = beg;
    for (; n + 4 <= end; n += 4) {
        int w0 = g_col[n + 0], w1 = g_col[n + 1], w2 = g_col[n + 2], w3 = g_col[n + 3];
        float2 a0 = __half22float2(src[w0 * 32 + lane]);
        float2 a1 = __half22float2(src[w1 * 32 + lane]);
        float2 a2 = __half22float2(src[w2 * 32 + lane]);
        float2 a3 = __half22float2(src[w3 * 32 + lane]);
        acc.x += (a0.x + a1.x) + (a2.x + a3.x);
        acc.y += (a0.y + a1.y) + (a2.y + a3.y);
    }
    for (; n < end; ++n) {
        float2 a = __half22float2(src[g_col[n] * 32 + lane]);
        acc.x += a.x;
        acc.y += a.y;
    }
    if (STAGE == 0) {
        float iv = g_inv[v];
        ((__half2*)g_efh)[v * 32 + lane] = __floats2half2_rn(acc.x * iv, acc.y * iv);
    } else {
        ((float2*)g_y)[v * 32 + lane] = acc;
    }
}

// ---------------- fused dense transform, 4 vertices per thread ---------------
__global__ __launch_bounds__(256) void transform_kernel(
    const float* __restrict__ Wgc, const float* __restrict__ bgc,
    const float* __restrict__ Wbi, const float* __restrict__ bbi,
    float* __restrict__ out, int l, int finalize) {
    __shared__ float sWg[64 * 64];   // transposed: sWg[k*64+j] = Wgc[l][j][k]
    __shared__ float sWb[64 * 64];
    __shared__ float sG[64 * 64];    // 64 vertices x 64 dims
    __shared__ float sH[64 * 64];
    __shared__ float sbg[64], sbb[64];

    const float* Wg = Wgc + l * 4096;
    const float* Wb = Wbi + l * 4096;
    for (int idx = threadIdx.x; idx < 4096; idx += 256) {
        int j = idx >> 6, k = idx & 63;
        sWg[k * 64 + j] = Wg[idx];
        sWb[k * 64 + j] = Wb[idx];
    }
    if (threadIdx.x < 64) {
        sbg[threadIdx.x] = bgc[l * 64 + threadIdx.x];
        sbb[threadIdx.x] = bbi[l * 64 + threadIdx.x];
    }
    __syncthreads();

    int grp = threadIdx.x >> 4;   // 16 groups of 16 lanes
    int c   = threadIdx.x & 15;   // output float4 chunk j = 4c..4c+3

    int vb = blockIdx.x * 64 + grp * 4;   // first of this group's 4 vertices (< NVP)

    float4 x4[4];
    float  sv[4];
#pragma unroll
    for (int u = 0; u < 4; ++u) {
        int v = vb + u;
        float s = g_isq[v];
        sv[u] = s;
        float4 y4 = ((const float4*)g_y)[v * 16 + c];
        x4[u] = ((const float4*)g_all)[v * 16 + c];
        float4 g4 = make_float4(y4.x * s, y4.y * s, y4.z * s, y4.w * s);
        float4 h4 = make_float4(g4.x * x4[u].x, g4.y * x4[u].y,
                                g4.z * x4[u].z, g4.w * x4[u].w);
        ((float4*)(sG + (grp * 4 + u) * 64))[c] = g4;
        ((float4*)(sH + (grp * 4 + u) * 64))[c] = h4;
    }
    __syncwarp();

    float4 o1[4], o2[4];
    {
        float4 bg = *(const float4*)(sbg + 4 * c);
        float4 bb = *(const float4*)(sbb + 4 * c);
#pragma unroll
        for (int u = 0; u < 4; ++u) { o1[u] = bg; o2[u] = bb; }
    }

#pragma unroll
    for (int k = 0; k < 64; k += 4) {
        float4 wa0 = *(const float4*)(sWg + (k + 0) * 64 + 4 * c);
        float4 wa1 = *(const float4*)(sWg + (k + 1) * 64 + 4 * c);
        float4 wa2 = *(const float4*)(sWg + (k + 2) * 64 + 4 * c);
        float4 wa3 = *(const float4*)(sWg + (k + 3) * 64 + 4 * c);
        float4 wb0 = *(const float4*)(sWb + (k + 0) * 64 + 4 * c);
        float4 wb1 = *(const float4*)(sWb + (k + 1) * 64 + 4 * c);
        float4 wb2 = *(const float4*)(sWb + (k + 2) * 64 + 4 * c);
        float4 wb3 = *(const float4*)(sWb + (k + 3) * 64 + 4 * c);
#pragma unroll
        for (int u = 0; u < 4; ++u) {
            const float* gb = sG + (grp * 4 + u) * 64;
            const float* hb = sH + (grp * 4 + u) * 64;
            float4 gk = *(const float4*)(gb + k);
            float4 hk = *(const float4*)(hb + k);
            o1[u].x = fmaf(gk.x, wa0.x, o1[u].x); o1[u].y = fmaf(gk.x, wa0.y, o1[u].y);
            o1[u].z = fmaf(gk.x, wa0.z, o1[u].z); o1[u].w = fmaf(gk.x, wa0.w, o1[u].w);
            o1[u].x = fmaf(gk.y, wa1.x, o1[u].x); o1[u].y = fmaf(gk.y, wa1.y, o1[u].y);
            o1[u].z = fmaf(gk.y, wa1.z, o1[u].z); o1[u].w = fmaf(gk.y, wa1.w, o1[u].w);
            o1[u].x = fmaf(gk.z, wa2.x, o1[u].x); o1[u].y = fmaf(gk.z, wa2.y, o1[u].y);
            o1[u].z = fmaf(gk.z, wa2.z, o1[u].z); o1[u].w = fmaf(gk.z, wa2.w, o1[u].w);
            o1[u].x = fmaf(gk.w, wa3.x, o1[u].x); o1[u].y = fmaf(gk.w, wa3.y, o1[u].y);
            o1[u].z = fmaf(gk.w, wa3.z, o1[u].z); o1[u].w = fmaf(gk.w, wa3.w, o1[u].w);
            o2[u].x = fmaf(hk.x, wb0.x, o2[u].x); o2[u].y = fmaf(hk.x, wb0.y, o2[u].y);
            o2[u].z = fmaf(hk.x, wb0.z, o2[u].z); o2[u].w = fmaf(hk.x, wb0.w, o2[u].w);
            o2[u].x = fmaf(hk.y, wb1.x, o2[u].x); o2[u].y = fmaf(hk.y, wb1.y, o2[u].y);
            o2[u].z = fmaf(hk.y, wb1.z, o2[u].z); o2[u].w = fmaf(hk.y, wb1.w, o2[u].w);
            o2[u].x = fmaf(hk.z, wb2.x, o2[u].x); o2[u].y = fmaf(hk.z, wb2.y, o2[u].y);
            o2[u].z = fmaf(hk.z, wb2.z, o2[u].z); o2[u].w = fmaf(hk.z, wb2.w, o2[u].w);
            o2[u].x = fmaf(hk.w, wb3.x, o2[u].x); o2[u].y = fmaf(hk.w, wb3.y, o2[u].y);
            o2[u].z = fmaf(hk.w, wb3.z, o2[u].z); o2[u].w = fmaf(hk.w, wb3.w, o2[u].w);
        }
    }

#pragma unroll
    for (int u = 0; u < 4; ++u) {
        int v = vb + u;
        float4 a = o1[u], b = o2[u];
        a.x += x4[u].x; a.y += x4[u].y; a.z += x4[u].z; a.w += x4[u].w;
        a.x = a.x > 0.f ? a.x : 0.2f * a.x;
        a.y = a.y > 0.f ? a.y : 0.2f * a.y;
        a.z = a.z > 0.f ? a.z : 0.2f * a.z;
        a.w = a.w > 0.f ? a.w : 0.2f * a.w;
        b.x = b.x > 0.f ? b.x : 0.2f * b.x;
        b.y = b.y > 0.f ? b.y : 0.2f * b.y;
        b.z = b.z > 0.f ? b.z : 0.2f * b.z;
        b.w = b.w > 0.f ? b.w : 0.2f * b.w;
        float4 nv = make_float4(a.x + b.x, a.y + b.y, a.z + b.z, a.w + b.w);
        float ss = nv.x * nv.x + nv.y * nv.y + nv.z * nv.z + nv.w * nv.w;
#pragma unroll
        for (int off = 8; off > 0; off >>= 1)
            ss += __shfl_xor_sync(0xffffffffu, ss, off);
        float r = 1.0f / fmaxf(sqrtf(ss), 1e-12f);
        nv.x *= r; nv.y *= r; nv.z *= r; nv.w *= r;

        ((float4*)g_all)[v * 16 + c] = nv;
        // fp16 copy pre-scaled by isq[v] for the next layer's stage-A gather
        float s = sv[u];
        ((__half2*)g_allh)[v * 32 + 2 * c + 0] = __floats2half2_rn(nv.x * s, nv.y * s);
        ((__half2*)g_allh)[v * 32 + 2 * c + 1] = __floats2half2_rn(nv.z * s, nv.w * s);

        if (v < NV) {
            float4 o = ((float4*)out)[v * 16 + c];
            o.x += nv.x; o.y += nv.y; o.z += nv.z; o.w += nv.w;
            if (finalize) { o.x *= 0.25f; o.y *= 0.25f; o.z *= 0.25f; o.w *= 0.25f; }
            ((float4*)out)[v * 16 + c] = o;
        }
    }
}

// ---------------- launch ------------------------------------------------------
extern "C" void kernel_launch(void* const* d_in, const int* in_sizes, int n_in,
                              void* d_out, int out_size) {
    const float* u_emb = (const float*)d_in[0];
    const float* i_emb = (const float*)d_in[1];
    const float* Wgc   = (const float*)d_in[2];
    const float* bgc   = (const float*)d_in[3];
    const float* Wbi   = (const float*)d_in[4];
    const float* bbi   = (const float*)d_in[5];
    const int*   eu    = (const int*)d_in[6];
    const int*   ei    = (const int*)d_in[7];
    float* out = (float*)d_out;

    const int VB = (NV + 255) / 256;
    const int EB = (NE + 255) / 256;
    const int IB = NV * 16 / 256;    // init: 9375 exact
    const int GB = NV * 32 / 256;    // gather: 18750 exact
    const int TB = NVP / 64;         // transform: 2344 exact (padded)

    zero_deg_kernel<<<VB, 256>>>();
    deg_kernel<<<EB, 256>>>(eu, ei);
    offsets_kernel<<<VB, 256>>>();
    scatter_kernel<<<EB, 256>>>(eu, ei);
    init_kernel<<<IB, 256>>>((const float4*)u_emb, (const float4*)i_emb, (float4*)out);

    for (int l = 0; l < 3; ++l) {
        gather_kernel<0><<<GB, 256>>>();
        gather_kernel<1><<<GB, 256>>>();
        transform_kernel<<<TB, 256>>>(Wgc, bgc, Wbi, bbi, out, l, l == 2 ? 1 : 0);
    }
}